// round 1
// baseline (speedup 1.0000x reference)
#include <cuda_runtime.h>

#define THRESH 0.3f
#define MARGIN 0.1f
#define WEIGHT 0.1f

#define NBLK 1184
#define NTHR 256

__device__ float g_partial_sum[NBLK];
__device__ int   g_partial_cnt[NBLK];

__device__ __forceinline__ void proc_row(float p4, float p5, float p6, float t,
                                         float& s, int& c) {
    bool a = p4 > THRESH;
    bool b = p5 > THRESH;
    bool d = p6 > THRESH;
    bool m45  = a && b;
    bool m56  = b && d;
    bool m456 = m45 && d;
    float d45 = p5 - p4;
    float d56 = p6 - p5;
    float t45 = fmaxf(MARGIN - t * d45, 0.0f);
    float t56 = fmaxf(MARGIN - t * d56, 0.0f);
    float tor = fmaxf(fabsf(d45) - fabsf(d56) + MARGIN, 0.0f);
    if (m45)  { s += t45; c++; }
    if (m56)  { s += t56; c++; }
    if (m456) { s += tor; c++; }
}

__global__ __launch_bounds__(NTHR) void loss_main_kernel(
    const float4* __restrict__ pred,   // [B,4] as float4 per row
    const float4* __restrict__ t4,     // [B] viewed as float4 (B % 4 == 0)
    int ngroups)                       // B / 4
{
    float s = 0.0f;
    int   c = 0;
    int stride = gridDim.x * blockDim.x;
    for (int g = blockIdx.x * blockDim.x + threadIdx.x; g < ngroups; g += stride) {
        float4 tt = t4[g];
        float4 p0 = pred[4 * g + 0];
        float4 p1 = pred[4 * g + 1];
        float4 p2 = pred[4 * g + 2];
        float4 p3 = pred[4 * g + 3];
        proc_row(p0.y, p0.z, p0.w, tt.x, s, c);
        proc_row(p1.y, p1.z, p1.w, tt.y, s, c);
        proc_row(p2.y, p2.z, p2.w, tt.z, s, c);
        proc_row(p3.y, p3.z, p3.w, tt.w, s, c);
    }

    // warp reduce
    #pragma unroll
    for (int o = 16; o > 0; o >>= 1) {
        s += __shfl_down_sync(0xFFFFFFFFu, s, o);
        c += __shfl_down_sync(0xFFFFFFFFu, c, o);
    }

    __shared__ float ws[NTHR / 32];
    __shared__ int   wc[NTHR / 32];
    int lane = threadIdx.x & 31;
    int wid  = threadIdx.x >> 5;
    if (lane == 0) { ws[wid] = s; wc[wid] = c; }
    __syncthreads();
    if (wid == 0) {
        s = (lane < NTHR / 32) ? ws[lane] : 0.0f;
        c = (lane < NTHR / 32) ? wc[lane] : 0;
        #pragma unroll
        for (int o = 4; o > 0; o >>= 1) {
            s += __shfl_down_sync(0xFFFFFFFFu, s, o);
            c += __shfl_down_sync(0xFFFFFFFFu, c, o);
        }
        if (lane == 0) {
            g_partial_sum[blockIdx.x] = s;
            g_partial_cnt[blockIdx.x] = c;
        }
    }
}

__global__ __launch_bounds__(1024) void loss_final_kernel(float* __restrict__ out)
{
    float s = 0.0f;
    int   c = 0;
    for (int i = threadIdx.x; i < NBLK; i += 1024) {
        s += g_partial_sum[i];
        c += g_partial_cnt[i];
    }
    #pragma unroll
    for (int o = 16; o > 0; o >>= 1) {
        s += __shfl_down_sync(0xFFFFFFFFu, s, o);
        c += __shfl_down_sync(0xFFFFFFFFu, c, o);
    }
    __shared__ float ws[32];
    __shared__ int   wc[32];
    int lane = threadIdx.x & 31;
    int wid  = threadIdx.x >> 5;
    if (lane == 0) { ws[wid] = s; wc[wid] = c; }
    __syncthreads();
    if (wid == 0) {
        s = (lane < 32) ? ws[lane] : 0.0f;
        c = (lane < 32) ? wc[lane] : 0;
        #pragma unroll
        for (int o = 16; o > 0; o >>= 1) {
            s += __shfl_down_sync(0xFFFFFFFFu, s, o);
            c += __shfl_down_sync(0xFFFFFFFFu, c, o);
        }
        if (lane == 0) {
            float cntf = (float)c;
            float loss = (c > 0) ? (s / fmaxf(cntf, 1.0f)) : s;
            out[0] = WEIGHT * loss;
        }
    }
}

extern "C" void kernel_launch(void* const* d_in, const int* in_sizes, int n_in,
                              void* d_out, int out_size)
{
    const float4* pred = (const float4*)d_in[0];     // predictions [B,4]
    const float4* t4   = (const float4*)d_in[1];     // relative_times [B,1]
    int B = in_sizes[1];                             // element count of relative_times
    int ngroups = B / 4;

    loss_main_kernel<<<NBLK, NTHR>>>(pred, t4, ngroups);
    loss_final_kernel<<<1, 1024>>>((float*)d_out);
}